// round 15
// baseline (speedup 1.0000x reference)
#include <cuda_runtime.h>
#include <cstdint>
#include <cstddef>

#define BN 16
#define HH 512
#define WW 512
#define NPIX (BN*HH*WW)          // 4194304
#define CNUM 6
#define LNUM 3
#define RINGN 2044               // ring pixels per sample
#define NTILE 2048               // build tiles: 4x512 (CSR granularity)
#define FTILE 512                // fused tiles: 16x512 (single wave)

// ---------------- static device scratch (no allocations allowed) ----------------
__device__ float    g_img[NPIX];                     // ping buffer A (raw space)
__device__ float    g_im2[NPIX];                     // pong buffer B (raw space)
__device__ unsigned g_list[(size_t)CNUM * NPIX];     // per-class interior pixel lists
__device__ unsigned g_cnt[CNUM];
__device__ unsigned g_toff[CNUM * NTILE];            // CSR: start of (cls,tile)
__device__ unsigned g_tcnt[CNUM * NTILE];            // CSR: count
__device__ unsigned g_mnu[BN], g_mxu[BN];            // order-encoded min/max bits
__device__ float    g_tbl[BN * CNUM * 128];          // folded raw-space table
__constant__ float4 cTbl[BN * CNUM * 32];            // same table, constant bank (48KB)

// ---------------- helpers ----------------
__device__ __forceinline__ unsigned fenc(float f) {
    unsigned b = __float_as_uint(f);
    return (b & 0x80000000u) ? ~b : (b | 0x80000000u);
}
__device__ __forceinline__ float fdec(unsigned u) {
    unsigned b = (u & 0x80000000u) ? (u ^ 0x80000000u) : ~u;
    return __uint_as_float(b);
}
__device__ __forceinline__ float sigm(float x) { return 1.0f / (1.0f + __expf(-x)); }

__device__ __forceinline__ float bez(float c, float mix,
                                     float p1, float p2, float p1v, float p2v) {
    float om  = 1.0f - c;
    float om2 = om * om, c2 = c * c;
    float ct = 3.0f * om2 * c * p1 + 3.0f * om * c2 * p2 + c2 * c;
    float cv = om2 * om + 3.0f * om2 * c * p1v + 3.0f * om * c2 * p2v;
    float v  = ct * mix + cv * (1.0f - mix);
    return fminf(fmaxf(v, 0.0f), 1.0f);
}

__device__ __forceinline__ void ring_yx(int q, int& y, int& x) {
    if (q < 512)       { y = 0;   x = q; }
    else if (q < 1024) { y = 511; x = q - 512; }
    else if (q < 1534) { x = 0;   y = q - 1023; }
    else               { x = 511; y = q - 1533; }
}

// ---------------- init counters/minmax atoms ----------------
__global__ void k_init() {
    int t = threadIdx.x;
    if (t < CNUM) g_cnt[t] = 0u;
    if (t < BN) { g_mnu[t] = 0xFFFFFFFFu; g_mxu[t] = 0u; }
}

// per-sample min/max
__global__ void k_minmax(const float4* __restrict__ x) {
    int b = blockIdx.x >> 3, chunk = blockIdx.x & 7;
    const float4* p = x + (size_t)b * 65536 + (size_t)chunk * 8192;
    float mn = 3.4e38f, mx = -3.4e38f;
    for (int i = threadIdx.x; i < 8192; i += 256) {
        float4 v = __ldg(p + i);
        mn = fminf(mn, fminf(fminf(v.x, v.y), fminf(v.z, v.w)));
        mx = fmaxf(mx, fmaxf(fmaxf(v.x, v.y), fmaxf(v.z, v.w)));
    }
    for (int o = 16; o; o >>= 1) {
        mn = fminf(mn, __shfl_down_sync(0xffffffffu, mn, o));
        mx = fmaxf(mx, __shfl_down_sync(0xffffffffu, mx, o));
    }
    __shared__ float smn[8], smx[8];
    if ((threadIdx.x & 31) == 0) { smn[threadIdx.x >> 5] = mn; smx[threadIdx.x >> 5] = mx; }
    __syncthreads();
    if (threadIdx.x == 0) {
        for (int w = 1; w < 8; w++) { mn = fminf(mn, smn[w]); mx = fmaxf(mx, smx[w]); }
        atomicMin(&g_mnu[b], fenc(mn));
        atomicMax(&g_mxu[b], fenc(mx));
    }
}

// ---------------- setup (AFTER minmax): effective 5x5 table folded to RAW space ----
// a_normspace = sum_j wef_j*(x_j-mn)*inv + beff  ==  sum_j (wef_j*inv)*x_j + (beff - mn*inv*sum_j wef_j)
__global__ void k_setup(const int* __restrict__ index, const float* __restrict__ param,
                        const float* __restrict__ w1, const float* __restrict__ b1,
                        const float* __restrict__ w2, const float* __restrict__ b2) {
    int t = threadIdx.x;
    if (t >= BN * CNUM * LNUM) return;
    int b = t / (CNUM * LNUM);
    int i = (t / LNUM) % CNUM;
    int l = t % LNUM;
    int d = __ldg(index + b);
    int k = ((d * CNUM + i) * 4) * LNUM + l;   // aug index fixed to 0
    const float* W1 = w1 + (size_t)k * 36;
    const float* W2 = w2 + (size_t)k * 36;
    const float* B1 = b1 + (size_t)k * 4;
    const float* P  = param + (size_t)k * 7;

    float wef[25];
#pragma unroll
    for (int j = 0; j < 25; j++) wef[j] = 0.0f;
    float beff = __ldg(b2 + k);
#pragma unroll
    for (int ch = 0; ch < 4; ch++) {
        float s2 = 0.0f;
#pragma unroll
        for (int e = 0; e < 9; e++) {
            float w2v = __ldg(W2 + ch * 9 + e);
            s2 += w2v;
            int ey = e / 3, ex = e % 3;
#pragma unroll
            for (int dd = 0; dd < 9; dd++) {
                wef[(ey + dd / 3) * 5 + (ex + dd % 3)] += w2v * __ldg(W1 + ch * 9 + dd);
            }
        }
        beff += __ldg(B1 + ch) * s2;
    }
    // fold per-sample normalization into weights (raw-space conv)
    float mn  = fdec(g_mnu[b]);
    float inv = 1.0f / (fdec(g_mxu[b]) - mn + 1e-8f);
    float wsum = 0.0f;
#pragma unroll
    for (int j = 0; j < 25; j++) wsum += wef[j];
    float beffR = beff - mn * inv * wsum;

    float* T = g_tbl + (size_t)(b * CNUM + i) * 128;
#pragma unroll
    for (int j = 0; j < 25; j++) T[j * 4 + l] = wef[j] * inv;
    T[100 + l] = beffR;
#pragma unroll
    for (int j = 0; j < 4; j++) T[104 + l * 4 + j] = sigm(__ldg(P + j));
    if (l == 0) {
        T[103] = 0.0f;
#pragma unroll
        for (int j = 0; j < 25; j++) T[j * 4 + 3] = 0.0f;
    }
}

// Per-class INTERIOR list build + per-(class,tile) CSR. Labels only.
__global__ void __launch_bounds__(256) k_build(const int* __restrict__ lbl) {
    __shared__ unsigned scur[CNUM];
    __shared__ unsigned sbase[CNUM];
    const int t = threadIdx.x;
    const int lane = t & 31;
    const unsigned base = blockIdx.x * 2048u;

    if (t < CNUM) scur[t] = 0u;
    __syncthreads();

    // pass A: counts (interior only), labels stashed
    int lc[8];
    unsigned c0 = 0, c1 = 0, c2 = 0, c3 = 0, c4 = 0, c5 = 0;
#pragma unroll
    for (int s = 0; s < 8; s++) {
        unsigned p = base + (unsigned)s * 256u + t;
        int c = __ldg(lbl + p);
        unsigned yy = (p >> 9) & 511u, xx = p & 511u;
        if (!((yy - 1u) < 510u && (xx - 1u) < 510u)) c = 6;   // ring -> excluded
        lc[s] = c;
        c0 += (c == 0); c1 += (c == 1); c2 += (c == 2);
        c3 += (c == 3); c4 += (c == 4); c5 += (c == 5);
    }
#pragma unroll
    for (int o = 16; o; o >>= 1) {
        c0 += __shfl_down_sync(0xffffffffu, c0, o);
        c1 += __shfl_down_sync(0xffffffffu, c1, o);
        c2 += __shfl_down_sync(0xffffffffu, c2, o);
        c3 += __shfl_down_sync(0xffffffffu, c3, o);
        c4 += __shfl_down_sync(0xffffffffu, c4, o);
        c5 += __shfl_down_sync(0xffffffffu, c5, o);
    }
    unsigned w0 = 0, w1o = 0, w2o = 0, w3o = 0, w4o = 0, w5o = 0;
    if (lane == 0) {
        w0  = atomicAdd(&scur[0], c0); w1o = atomicAdd(&scur[1], c1);
        w2o = atomicAdd(&scur[2], c2); w3o = atomicAdd(&scur[3], c3);
        w4o = atomicAdd(&scur[4], c4); w5o = atomicAdd(&scur[5], c5);
    }
    __syncthreads();
    if (t < CNUM) {
        unsigned tot = scur[t];
        unsigned gb = atomicAdd(&g_cnt[t], tot);
        sbase[t] = gb;
        g_toff[t * NTILE + blockIdx.x] = gb;
        g_tcnt[t * NTILE + blockIdx.x] = tot;
    }
    __syncthreads();
    unsigned r0 = sbase[0] + __shfl_sync(0xffffffffu, w0, 0);
    unsigned r1 = sbase[1] + __shfl_sync(0xffffffffu, w1o, 0);
    unsigned r2 = sbase[2] + __shfl_sync(0xffffffffu, w2o, 0);
    unsigned r3 = sbase[3] + __shfl_sync(0xffffffffu, w3o, 0);
    unsigned r4 = sbase[4] + __shfl_sync(0xffffffffu, w4o, 0);
    unsigned r5 = sbase[5] + __shfl_sync(0xffffffffu, w5o, 0);
    const unsigned lmask = (1u << lane) - 1u;

    // pass B: atomic-free emit
#pragma unroll
    for (int s = 0; s < 8; s++) {
        unsigned p = base + (unsigned)s * 256u + t;
        int myc = lc[s];
        unsigned m;
        m = __ballot_sync(0xffffffffu, myc == 0);
        if (myc == 0) g_list[0 * (size_t)NPIX + r0 + __popc(m & lmask)] = p;
        r0 += __popc(m);
        m = __ballot_sync(0xffffffffu, myc == 1);
        if (myc == 1) g_list[1 * (size_t)NPIX + r1 + __popc(m & lmask)] = p;
        r1 += __popc(m);
        m = __ballot_sync(0xffffffffu, myc == 2);
        if (myc == 2) g_list[2 * (size_t)NPIX + r2 + __popc(m & lmask)] = p;
        r2 += __popc(m);
        m = __ballot_sync(0xffffffffu, myc == 3);
        if (myc == 3) g_list[3 * (size_t)NPIX + r3 + __popc(m & lmask)] = p;
        r3 += __popc(m);
        m = __ballot_sync(0xffffffffu, myc == 4);
        if (myc == 4) g_list[4 * (size_t)NPIX + r4 + __popc(m & lmask)] = p;
        r4 += __popc(m);
        m = __ballot_sync(0xffffffffu, myc == 5);
        if (myc == 5) g_list[5 * (size_t)NPIX + r5 + __popc(m & lmask)] = p;
        r5 += __popc(m);
    }
}

// Slim fused per-class pass, 16-row tiles (single-wave grid of 512):
//  - 20-row halo -> smem, padded with mn (normalized zero) at image borders
//  - band seeded straight to dst during halo load
//  - composed raw-space 5x5 x 3 layers; weights/params from __constant__
//  - center normalized on the fly; result written raw to dst
__global__ void __launch_bounds__(256, 5) k_fused(int cls,
        const float* __restrict__ src, float* __restrict__ dst) {
    __shared__ float srow[20][520];    // data cols [4..515]; mn at [2..3],[516..517]

    const int tile = blockIdx.x;       // 0..511
    const int b  = tile >> 5;          // 32 bands per sample
    const int y0 = (tile & 31) << 4;

    const float mn  = fdec(g_mnu[b]);
    const float sc  = fdec(g_mxu[b]) - mn + 1e-8f;
    const float inv = 1.0f / sc;

    const float4* s4 = reinterpret_cast<const float4*>(src) + (size_t)b * 65536;
    float4*       d4 = reinterpret_cast<float4*>(dst) + (size_t)b * 65536;

    // halo load (20 rows x 128 float4) + direct band seed to dst
#pragma unroll
    for (int k = 0; k < 10; k++) {
        int idx = threadIdx.x + k * 256;      // 0..2559
        int r = idx >> 7, xq = idx & 127;
        int y = y0 - 2 + r;
        float4 v = (y >= 0 && y < HH) ? __ldg(s4 + y * 128 + xq)
                                      : make_float4(mn, mn, mn, mn);
        *reinterpret_cast<float4*>(&srow[r][4 + xq * 4]) = v;
        if (r >= 2 && r < 18) d4[y * 128 + xq] = v;
    }
    if (threadIdx.x < 20) {
        srow[threadIdx.x][2] = mn;   srow[threadIdx.x][3] = mn;
        srow[threadIdx.x][516] = mn; srow[threadIdx.x][517] = mn;
    }
    __syncthreads();

    const int cb = (b * CNUM + cls) * 32;     // uniform constant index
    const unsigned* __restrict__ list = g_list + (size_t)cls * NPIX;

#pragma unroll
    for (int h = 0; h < 4; h++) {
        const int ct = 4 * tile + h;          // CSR tile (4-row granularity)
        const unsigned off = g_toff[cls * NTILE + ct];
        const unsigned cnt = g_tcnt[cls * NTILE + ct];
        for (unsigned j = off + threadIdx.x; j < off + cnt; j += 256) {
            unsigned p = __ldg(list + j);
            int lx = (int)(p & 511u) + 4;
            int ly = (int)((p >> 9) & 511u) - y0 + 2;   // 2..17

            float4 bb4 = cTbl[cb + 25];
            float a0 = bb4.x, a1 = bb4.y, a2 = bb4.z;
#pragma unroll
            for (int r = 0; r < 5; r++) {
                const float* row = &srow[ly - 2 + r][lx - 2];
#pragma unroll
                for (int cix = 0; cix < 5; cix++) {
                    float v = row[cix];
                    float4 w = cTbl[cb + r * 5 + cix];
                    a0 += v * w.x; a1 += v * w.y; a2 += v * w.z;
                }
            }
            float cc = (srow[ly][lx] - mn) * inv;       // normalized center
            float4 pA = cTbl[cb + 26], pB = cTbl[cb + 27], pC = cTbl[cb + 28];
            cc = bez(cc, sigm(a0), pA.x, pA.y, pA.z, pA.w);
            cc = bez(cc, sigm(a1), pB.x, pB.y, pB.z, pB.w);
            cc = bez(cc, sigm(a2), pC.x, pC.y, pC.z, pC.w);
            dst[p] = cc * sc + mn;                      // back to raw space
        }
    }
}

// Border ring: exact two-step conv; neighbors normalized on load (zero-pad is
// zero in normalized space). Writes labeled ring pixels of dst raw.
__global__ void k_ring(int cls, const float* __restrict__ src,
                       float* __restrict__ dst, const int* __restrict__ lbl,
                       const int* __restrict__ index,
                       const float* __restrict__ w1, const float* __restrict__ b1,
                       const float* __restrict__ w2, const float* __restrict__ b2) {
    int r = blockIdx.x * 256 + threadIdx.x;
    if (r >= BN * RINGN) return;
    int b = r / RINGN, q = r % RINGN;
    int y, x;
    ring_yx(q, y, x);
    unsigned p = ((unsigned)b << 18) | ((unsigned)y << 9) | (unsigned)x;
    if (__ldg(lbl + p) != cls) return;

    const float mn  = fdec(g_mnu[b]);
    const float sc  = fdec(g_mxu[b]) - mn + 1e-8f;
    const float inv = 1.0f / sc;

    const float* basep = src + ((size_t)b << 18);
    float nb[25];
#pragma unroll
    for (int t = 0; t < 25; t++) {
        int yy = y + t / 5 - 2, xx = x + t % 5 - 2;
        nb[t] = (yy >= 0 && yy < HH && xx >= 0 && xx < WW)
                ? (__ldg(basep + yy * WW + xx) - mn) * inv : 0.0f;
    }
    float cc = nb[12];
    int d = __ldg(index + b);
    int kb = ((d * CNUM + cls) * 4) * LNUM;
    const float* T = g_tbl + (size_t)(b * CNUM + cls) * 128;
#pragma unroll
    for (int l = 0; l < LNUM; l++) {
        int k = kb + l;
        const float* W1 = w1 + (size_t)k * 36;
        const float* W2 = w2 + (size_t)k * 36;
        const float* B1 = b1 + (size_t)k * 4;
        float acc = __ldg(b2 + k);
#pragma unroll
        for (int e = 0; e < 9; e++) {
            int ey = e / 3 - 1, ex = e % 3 - 1;
            int qy = y + ey, qx = x + ex;
            if (qy < 0 || qy >= HH || qx < 0 || qx >= WW) continue;
            float hs = 0.0f;
#pragma unroll
            for (int ch = 0; ch < 4; ch++) {
                float h = __ldg(B1 + ch);
#pragma unroll
                for (int dd = 0; dd < 9; dd++) {
                    int dy = dd / 3 - 1, dx = dd % 3 - 1;
                    h += __ldg(W1 + ch * 9 + dd) * nb[(2 + ey + dy) * 5 + (2 + ex + dx)];
                }
                hs += h * __ldg(W2 + ch * 9 + e);
            }
            acc += hs;
        }
        cc = bez(cc, sigm(acc), T[104 + l * 4], T[105 + l * 4],
                 T[106 + l * 4], T[107 + l * 4]);
    }
    dst[p] = cc * sc + mn;
}

// ---------------- launch ----------------
extern "C" void kernel_launch(void* const* d_in, const int* in_sizes, int n_in,
                              void* d_out, int out_size) {
    const float* x     = (const float*)d_in[0];
    const int*   lbl   = (const int*)d_in[1];
    const int*   index = (const int*)d_in[2];
    const float* param = (const float*)d_in[3];
    const float* w1    = (const float*)d_in[4];
    const float* b1    = (const float*)d_in[5];
    const float* w2    = (const float*)d_in[6];
    const float* b2    = (const float*)d_in[7];
    float*       out   = (float*)d_out;

    void *pA = nullptr, *pB = nullptr, *cdst = nullptr, *csrc = nullptr;
    cudaGetSymbolAddress(&pA, g_img);
    cudaGetSymbolAddress(&pB, g_im2);
    cudaGetSymbolAddress(&cdst, cTbl);
    cudaGetSymbolAddress(&csrc, g_tbl);
    float* A = (float*)pA;
    float* B = (float*)pB;

    k_init<<<1, 64>>>();
    k_minmax<<<BN * 8, 256>>>((const float4*)x);
    k_setup<<<1, 288>>>(index, param, w1, b1, w2, b2);
    cudaMemcpyAsync(cdst, csrc, sizeof(float) * BN * CNUM * 128,
                    cudaMemcpyDeviceToDevice);
    k_build<<<NTILE, 256>>>(lbl);

    // ping-pong chain: x -> A -> B -> A -> B -> A -> out
    const float* srcs[CNUM] = { x, A, B, A, B, A };
    float*       dsts[CNUM] = { A, B, A, B, A, out };
    const int ringBlocks = (BN * RINGN + 255) / 256;  // 128
    for (int c = 0; c < CNUM; c++) {
        k_fused<<<FTILE, 256>>>(c, srcs[c], dsts[c]);
        k_ring<<<ringBlocks, 256>>>(c, srcs[c], dsts[c], lbl, index, w1, b1, w2, b2);
    }
}

// round 16
// speedup vs baseline: 1.1645x; 1.1645x over previous
#include <cuda_runtime.h>
#include <cstdint>
#include <cstddef>

#define BN 16
#define HH 512
#define WW 512
#define NPIX (BN*HH*WW)          // 4194304
#define CNUM 6
#define LNUM 3
#define RINGN 2044               // ring pixels per sample
#define NTILE 2048               // build tiles: 4x512 (CSR granularity)
#define FTILE 1024               // fused tiles: 8x512
#define RBLK 128                 // ring blocks (16*2044 / 256)

// ---------------- static device scratch (no allocations allowed) ----------------
__device__ float    g_img[NPIX];                     // ping buffer A (raw space)
__device__ float    g_im2[NPIX];                     // pong buffer B (raw space)
__device__ unsigned g_list[(size_t)CNUM * NPIX];     // per-class interior pixel lists
__device__ unsigned g_cnt[CNUM];
__device__ unsigned g_toff[CNUM * NTILE];            // CSR: start of (cls,tile)
__device__ unsigned g_tcnt[CNUM * NTILE];            // CSR: count
__device__ unsigned g_mnu[BN], g_mxu[BN];            // order-encoded min/max bits
__device__ float    g_tbl[BN * CNUM * 128];          // folded raw-space table
__constant__ float4 cTbl[BN * CNUM * 32];            // same table, constant bank (48KB)

// ---------------- helpers ----------------
__device__ __forceinline__ unsigned fenc(float f) {
    unsigned b = __float_as_uint(f);
    return (b & 0x80000000u) ? ~b : (b | 0x80000000u);
}
__device__ __forceinline__ float fdec(unsigned u) {
    unsigned b = (u & 0x80000000u) ? (u ^ 0x80000000u) : ~u;
    return __uint_as_float(b);
}
__device__ __forceinline__ float sigm(float x) { return 1.0f / (1.0f + __expf(-x)); }

__device__ __forceinline__ float bez(float c, float mix,
                                     float p1, float p2, float p1v, float p2v) {
    float om  = 1.0f - c;
    float om2 = om * om, c2 = c * c;
    float ct = 3.0f * om2 * c * p1 + 3.0f * om * c2 * p2 + c2 * c;
    float cv = om2 * om + 3.0f * om2 * c * p1v + 3.0f * om * c2 * p2v;
    float v  = ct * mix + cv * (1.0f - mix);
    return fminf(fmaxf(v, 0.0f), 1.0f);
}

__device__ __forceinline__ void ring_yx(int q, int& y, int& x) {
    if (q < 512)       { y = 0;   x = q; }
    else if (q < 1024) { y = 511; x = q - 512; }
    else if (q < 1534) { x = 0;   y = q - 1023; }
    else               { x = 511; y = q - 1533; }
}

// ---------------- init counters/minmax atoms ----------------
__global__ void k_init() {
    int t = threadIdx.x;
    if (t < CNUM) g_cnt[t] = 0u;
    if (t < BN) { g_mnu[t] = 0xFFFFFFFFu; g_mxu[t] = 0u; }
}

// per-sample min/max
__global__ void k_minmax(const float4* __restrict__ x) {
    int b = blockIdx.x >> 3, chunk = blockIdx.x & 7;
    const float4* p = x + (size_t)b * 65536 + (size_t)chunk * 8192;
    float mn = 3.4e38f, mx = -3.4e38f;
    for (int i = threadIdx.x; i < 8192; i += 256) {
        float4 v = __ldg(p + i);
        mn = fminf(mn, fminf(fminf(v.x, v.y), fminf(v.z, v.w)));
        mx = fmaxf(mx, fmaxf(fmaxf(v.x, v.y), fmaxf(v.z, v.w)));
    }
    for (int o = 16; o; o >>= 1) {
        mn = fminf(mn, __shfl_down_sync(0xffffffffu, mn, o));
        mx = fmaxf(mx, __shfl_down_sync(0xffffffffu, mx, o));
    }
    __shared__ float smn[8], smx[8];
    if ((threadIdx.x & 31) == 0) { smn[threadIdx.x >> 5] = mn; smx[threadIdx.x >> 5] = mx; }
    __syncthreads();
    if (threadIdx.x == 0) {
        for (int w = 1; w < 8; w++) { mn = fminf(mn, smn[w]); mx = fmaxf(mx, smx[w]); }
        atomicMin(&g_mnu[b], fenc(mn));
        atomicMax(&g_mxu[b], fenc(mx));
    }
}

// ---------------- setup (AFTER minmax): effective 5x5 table folded to RAW space ----
__global__ void k_setup(const int* __restrict__ index, const float* __restrict__ param,
                        const float* __restrict__ w1, const float* __restrict__ b1,
                        const float* __restrict__ w2, const float* __restrict__ b2) {
    int t = threadIdx.x;
    if (t >= BN * CNUM * LNUM) return;
    int b = t / (CNUM * LNUM);
    int i = (t / LNUM) % CNUM;
    int l = t % LNUM;
    int d = __ldg(index + b);
    int k = ((d * CNUM + i) * 4) * LNUM + l;   // aug index fixed to 0
    const float* W1 = w1 + (size_t)k * 36;
    const float* W2 = w2 + (size_t)k * 36;
    const float* B1 = b1 + (size_t)k * 4;
    const float* P  = param + (size_t)k * 7;

    float wef[25];
#pragma unroll
    for (int j = 0; j < 25; j++) wef[j] = 0.0f;
    float beff = __ldg(b2 + k);
#pragma unroll
    for (int ch = 0; ch < 4; ch++) {
        float s2 = 0.0f;
#pragma unroll
        for (int e = 0; e < 9; e++) {
            float w2v = __ldg(W2 + ch * 9 + e);
            s2 += w2v;
            int ey = e / 3, ex = e % 3;
#pragma unroll
            for (int dd = 0; dd < 9; dd++) {
                wef[(ey + dd / 3) * 5 + (ex + dd % 3)] += w2v * __ldg(W1 + ch * 9 + dd);
            }
        }
        beff += __ldg(B1 + ch) * s2;
    }
    float mn  = fdec(g_mnu[b]);
    float inv = 1.0f / (fdec(g_mxu[b]) - mn + 1e-8f);
    float wsum = 0.0f;
#pragma unroll
    for (int j = 0; j < 25; j++) wsum += wef[j];
    float beffR = beff - mn * inv * wsum;

    float* T = g_tbl + (size_t)(b * CNUM + i) * 128;
#pragma unroll
    for (int j = 0; j < 25; j++) T[j * 4 + l] = wef[j] * inv;
    T[100 + l] = beffR;
#pragma unroll
    for (int j = 0; j < 4; j++) T[104 + l * 4 + j] = sigm(__ldg(P + j));
    if (l == 0) {
        T[103] = 0.0f;
#pragma unroll
        for (int j = 0; j < 25; j++) T[j * 4 + 3] = 0.0f;
    }
}

// Per-class INTERIOR list build + per-(class,tile) CSR. 3-ballot emit.
__global__ void __launch_bounds__(256) k_build(const int* __restrict__ lbl) {
    __shared__ unsigned scur[CNUM];
    __shared__ unsigned sbase[CNUM];
    const int t = threadIdx.x;
    const int lane = t & 31;
    const unsigned base = blockIdx.x * 2048u;

    if (t < CNUM) scur[t] = 0u;
    __syncthreads();

    // pass A: counts (interior only), labels stashed
    int lc[8];
    unsigned c0 = 0, c1 = 0, c2 = 0, c3 = 0, c4 = 0, c5 = 0;
#pragma unroll
    for (int s = 0; s < 8; s++) {
        unsigned p = base + (unsigned)s * 256u + t;
        int c = __ldg(lbl + p);
        unsigned yy = (p >> 9) & 511u, xx = p & 511u;
        if (!((yy - 1u) < 510u && (xx - 1u) < 510u)) c = 6;   // ring -> excluded
        lc[s] = c;
        c0 += (c == 0); c1 += (c == 1); c2 += (c == 2);
        c3 += (c == 3); c4 += (c == 4); c5 += (c == 5);
    }
#pragma unroll
    for (int o = 16; o; o >>= 1) {
        c0 += __shfl_down_sync(0xffffffffu, c0, o);
        c1 += __shfl_down_sync(0xffffffffu, c1, o);
        c2 += __shfl_down_sync(0xffffffffu, c2, o);
        c3 += __shfl_down_sync(0xffffffffu, c3, o);
        c4 += __shfl_down_sync(0xffffffffu, c4, o);
        c5 += __shfl_down_sync(0xffffffffu, c5, o);
    }
    unsigned w0 = 0, w1o = 0, w2o = 0, w3o = 0, w4o = 0, w5o = 0;
    if (lane == 0) {
        w0  = atomicAdd(&scur[0], c0); w1o = atomicAdd(&scur[1], c1);
        w2o = atomicAdd(&scur[2], c2); w3o = atomicAdd(&scur[3], c3);
        w4o = atomicAdd(&scur[4], c4); w5o = atomicAdd(&scur[5], c5);
    }
    __syncthreads();
    if (t < CNUM) {
        unsigned tot = scur[t];
        unsigned gb = atomicAdd(&g_cnt[t], tot);
        sbase[t] = gb;
        g_toff[t * NTILE + blockIdx.x] = gb;
        g_tcnt[t * NTILE + blockIdx.x] = tot;
    }
    __syncthreads();
    unsigned r0 = sbase[0] + __shfl_sync(0xffffffffu, w0, 0);
    unsigned r1 = sbase[1] + __shfl_sync(0xffffffffu, w1o, 0);
    unsigned r2 = sbase[2] + __shfl_sync(0xffffffffu, w2o, 0);
    unsigned r3 = sbase[3] + __shfl_sync(0xffffffffu, w3o, 0);
    unsigned r4 = sbase[4] + __shfl_sync(0xffffffffu, w4o, 0);
    unsigned r5 = sbase[5] + __shfl_sync(0xffffffffu, w5o, 0);
    const unsigned lmask = (1u << lane) - 1u;

    // pass B: 3 ballots -> 6 class masks (labels are 3 bits; 6/7 self-exclude)
#pragma unroll
    for (int s = 0; s < 8; s++) {
        unsigned p = base + (unsigned)s * 256u + t;
        int myc = lc[s];
        unsigned b0 = __ballot_sync(0xffffffffu, myc & 1);
        unsigned b1 = __ballot_sync(0xffffffffu, myc & 2);
        unsigned b2 = __ballot_sync(0xffffffffu, myc & 4);
        unsigned m;
        m = ~b0 & ~b1 & ~b2;
        if (myc == 0) g_list[0 * (size_t)NPIX + r0 + __popc(m & lmask)] = p;
        r0 += __popc(m);
        m = b0 & ~b1 & ~b2;
        if (myc == 1) g_list[1 * (size_t)NPIX + r1 + __popc(m & lmask)] = p;
        r1 += __popc(m);
        m = ~b0 & b1 & ~b2;
        if (myc == 2) g_list[2 * (size_t)NPIX + r2 + __popc(m & lmask)] = p;
        r2 += __popc(m);
        m = b0 & b1 & ~b2;
        if (myc == 3) g_list[3 * (size_t)NPIX + r3 + __popc(m & lmask)] = p;
        r3 += __popc(m);
        m = ~b0 & ~b1 & b2;
        if (myc == 4) g_list[4 * (size_t)NPIX + r4 + __popc(m & lmask)] = p;
        r4 += __popc(m);
        m = b0 & ~b1 & b2;
        if (myc == 5) g_list[5 * (size_t)NPIX + r5 + __popc(m & lmask)] = p;
        r5 += __popc(m);
    }
}

// Fused per-class pass. Blocks [0,RBLK): ring pixels (exact two-step conv for
// labeled, copy for unlabeled — sole writers of ring pixels). Blocks >= RBLK:
// 8x512 interior tiles: halo->smem (mn-padded), composed raw-space 5x5 x3,
// band seed to dst skipping ring pixels, results direct to dst.
__global__ void __launch_bounds__(256, 5) k_fused(int cls,
        const float* __restrict__ src, float* __restrict__ dst,
        const int* __restrict__ lbl, const int* __restrict__ index,
        const float* __restrict__ w1, const float* __restrict__ b1,
        const float* __restrict__ w2, const float* __restrict__ b2) {
    if (blockIdx.x < RBLK) {
        // ---- ring path (block-uniform branch; no smem, spills OK) ----
        int r = blockIdx.x * 256 + threadIdx.x;
        if (r >= BN * RINGN) return;
        int b = r / RINGN, q = r % RINGN;
        int y, x;
        ring_yx(q, y, x);
        unsigned p = ((unsigned)b << 18) | ((unsigned)y << 9) | (unsigned)x;
        float srcv = __ldg(src + p);
        if (__ldg(lbl + p) != cls) { dst[p] = srcv; return; }

        const float mn  = fdec(g_mnu[b]);
        const float sc  = fdec(g_mxu[b]) - mn + 1e-8f;
        const float inv = 1.0f / sc;
        const float* basep = src + ((size_t)b << 18);
        float nb[25];
#pragma unroll
        for (int t = 0; t < 25; t++) {
            int yy = y + t / 5 - 2, xx = x + t % 5 - 2;
            nb[t] = (yy >= 0 && yy < HH && xx >= 0 && xx < WW)
                    ? (__ldg(basep + yy * WW + xx) - mn) * inv : 0.0f;
        }
        float cc = nb[12];
        int d = __ldg(index + b);
        int kb = ((d * CNUM + cls) * 4) * LNUM;
        const float* T = g_tbl + (size_t)(b * CNUM + cls) * 128;
#pragma unroll
        for (int l = 0; l < LNUM; l++) {
            int k = kb + l;
            const float* W1 = w1 + (size_t)k * 36;
            const float* W2 = w2 + (size_t)k * 36;
            const float* B1 = b1 + (size_t)k * 4;
            float acc = __ldg(b2 + k);
#pragma unroll
            for (int e = 0; e < 9; e++) {
                int ey = e / 3 - 1, ex = e % 3 - 1;
                int qy = y + ey, qx = x + ex;
                if (qy < 0 || qy >= HH || qx < 0 || qx >= WW) continue;
                float hs = 0.0f;
#pragma unroll
                for (int ch = 0; ch < 4; ch++) {
                    float h = __ldg(B1 + ch);
#pragma unroll
                    for (int dd = 0; dd < 9; dd++) {
                        int dy = dd / 3 - 1, dx = dd % 3 - 1;
                        h += __ldg(W1 + ch * 9 + dd) * nb[(2 + ey + dy) * 5 + (2 + ex + dx)];
                    }
                    hs += h * __ldg(W2 + ch * 9 + e);
                }
                acc += hs;
            }
            cc = bez(cc, sigm(acc), T[104 + l * 4], T[105 + l * 4],
                     T[106 + l * 4], T[107 + l * 4]);
        }
        dst[p] = cc * sc + mn;
        return;
    }

    // ---- interior path ----
    __shared__ float srow[12][520];    // data cols [4..515]; mn at [2..3],[516..517]
    const int tile = blockIdx.x - RBLK;   // 0..1023
    const int b  = tile >> 6;             // 64 bands per sample
    const int y0 = (tile & 63) << 3;

    const float mn  = fdec(g_mnu[b]);
    const float sc  = fdec(g_mxu[b]) - mn + 1e-8f;
    const float inv = 1.0f / sc;

    const float4* s4 = reinterpret_cast<const float4*>(src) + (size_t)b * 65536;
    float* drow = dst + ((size_t)b << 18);

    // halo load (12 rows x 128 float4) + band seed to dst EXCLUDING ring pixels
#pragma unroll
    for (int k = 0; k < 6; k++) {
        int idx = threadIdx.x + k * 256;      // 0..1535
        int r = idx >> 7, xq = idx & 127;
        int y = y0 - 2 + r;
        float4 v = (y >= 0 && y < HH) ? __ldg(s4 + y * 128 + xq)
                                      : make_float4(mn, mn, mn, mn);
        *reinterpret_cast<float4*>(&srow[r][4 + xq * 4]) = v;
        if (r >= 2 && r < 10 && y != 0 && y != 511) {
            float* dr = drow + y * WW;
            if (xq == 0)        { dr[1] = v.y; dr[2] = v.z; dr[3] = v.w; }
            else if (xq == 127) { dr[508] = v.x; dr[509] = v.y; dr[510] = v.z; }
            else *reinterpret_cast<float4*>(dr + xq * 4) = v;
        }
    }
    if (threadIdx.x < 12) {
        srow[threadIdx.x][2] = mn;   srow[threadIdx.x][3] = mn;
        srow[threadIdx.x][516] = mn; srow[threadIdx.x][517] = mn;
    }
    __syncthreads();

    const int cb = (b * CNUM + cls) * 32;     // uniform constant index
    const unsigned* __restrict__ list = g_list + (size_t)cls * NPIX;

#pragma unroll
    for (int h = 0; h < 2; h++) {
        const int ct = 2 * tile + h;          // CSR tile (4-row granularity)
        const unsigned off = g_toff[cls * NTILE + ct];
        const unsigned cnt = g_tcnt[cls * NTILE + ct];
        for (unsigned j = off + threadIdx.x; j < off + cnt; j += 256) {
            unsigned p = __ldg(list + j);
            int lx = (int)(p & 511u) + 4;
            int ly = (int)((p >> 9) & 511u) - y0 + 2;   // 2..9

            float4 bb4 = cTbl[cb + 25];
            float a0 = bb4.x, a1 = bb4.y, a2 = bb4.z;
#pragma unroll
            for (int r = 0; r < 5; r++) {
                const float* row = &srow[ly - 2 + r][lx - 2];
#pragma unroll
                for (int cix = 0; cix < 5; cix++) {
                    float v = row[cix];
                    float4 w = cTbl[cb + r * 5 + cix];
                    a0 += v * w.x; a1 += v * w.y; a2 += v * w.z;
                }
            }
            float cc = (srow[ly][lx] - mn) * inv;       // normalized center
            float4 pA = cTbl[cb + 26], pB = cTbl[cb + 27], pC = cTbl[cb + 28];
            cc = bez(cc, sigm(a0), pA.x, pA.y, pA.z, pA.w);
            cc = bez(cc, sigm(a1), pB.x, pB.y, pB.z, pB.w);
            cc = bez(cc, sigm(a2), pC.x, pC.y, pC.z, pC.w);
            dst[p] = cc * sc + mn;                      // back to raw space
        }
    }
}

// ---------------- launch ----------------
extern "C" void kernel_launch(void* const* d_in, const int* in_sizes, int n_in,
                              void* d_out, int out_size) {
    const float* x     = (const float*)d_in[0];
    const int*   lbl   = (const int*)d_in[1];
    const int*   index = (const int*)d_in[2];
    const float* param = (const float*)d_in[3];
    const float* w1    = (const float*)d_in[4];
    const float* b1    = (const float*)d_in[5];
    const float* w2    = (const float*)d_in[6];
    const float* b2    = (const float*)d_in[7];
    float*       out   = (float*)d_out;

    void *pA = nullptr, *pB = nullptr, *cdst = nullptr, *csrc = nullptr;
    cudaGetSymbolAddress(&pA, g_img);
    cudaGetSymbolAddress(&pB, g_im2);
    cudaGetSymbolAddress(&cdst, cTbl);
    cudaGetSymbolAddress(&csrc, g_tbl);
    float* A = (float*)pA;
    float* B = (float*)pB;

    k_init<<<1, 64>>>();
    k_minmax<<<BN * 8, 256>>>((const float4*)x);
    k_setup<<<1, 288>>>(index, param, w1, b1, w2, b2);
    cudaMemcpyAsync(cdst, csrc, sizeof(float) * BN * CNUM * 128,
                    cudaMemcpyDeviceToDevice);
    k_build<<<NTILE, 256>>>(lbl);

    // ping-pong chain: x -> A -> B -> A -> B -> A -> out
    const float* srcs[CNUM] = { x, A, B, A, B, A };
    float*       dsts[CNUM] = { A, B, A, B, A, out };
    for (int c = 0; c < CNUM; c++)
        k_fused<<<FTILE + RBLK, 256>>>(c, srcs[c], dsts[c], lbl, index,
                                       w1, b1, w2, b2);
}